// round 9
// baseline (speedup 1.0000x reference)
#include <cuda_runtime.h>
#include <cstdint>

#define HEADS 16
#define DIMD 128
#define NSEQ 2048
/* exp(x*INV_SQRT_N) == exp2(x*C2) */
#define C2 0.0318793576f
#define KSPLIT 16

// ---------------- scratch (static device globals; no allocations) ----------------
__device__ __align__(16) uint32_t g_qp2[HEADS * NSEQ * 64];  // f16x2 packed
__device__ __align__(16) uint32_t g_kp2[HEADS * NSEQ * 64];  // f16x2 packed
__device__ __align__(16) uint32_t g_vp2[HEADS * NSEQ * 64];  // f16x2 packed
__device__ __align__(16) float g_ctx[NSEQ * HEADS * DIMD];
__device__ __align__(16) float g_part[KSPLIT * NSEQ * DIMD];
__device__ __align__(16) unsigned g_mbits[(NSEQ / 32) * NSEQ];  // [word][row]

// ---------------- helpers ----------------
__device__ __forceinline__ uint32_t f2tf(float x) {
  uint32_t r;
  asm("cvt.rna.tf32.f32 %0, %1;" : "=r"(r) : "f"(x));
  return r;
}
__device__ __forceinline__ uint32_t f2h2(float lo, float hi) {
  uint32_t r;
  asm("cvt.rn.f16x2.f32 %0, %1, %2;" : "=r"(r) : "f"(hi), "f"(lo));
  return r;
}
__device__ __forceinline__ uint32_t smem_u32(const void* p) {
  uint32_t a;
  asm("{ .reg .u64 t; cvta.to.shared.u64 t, %1; cvt.u32.u64 %0, t; }" : "=r"(a) : "l"(p));
  return a;
}

__device__ __forceinline__ void mma_tf32(float c[4], const uint32_t a[4],
                                         uint32_t b0, uint32_t b1) {
  asm volatile(
      "mma.sync.aligned.m16n8k8.row.col.f32.tf32.tf32.f32 "
      "{%0,%1,%2,%3}, {%4,%5,%6,%7}, {%8,%9}, {%0,%1,%2,%3};"
      : "+f"(c[0]), "+f"(c[1]), "+f"(c[2]), "+f"(c[3])
      : "r"(a[0]), "r"(a[1]), "r"(a[2]), "r"(a[3]), "r"(b0), "r"(b1));
}

__device__ __forceinline__ void mma_f16(float c[4], const uint32_t a[4],
                                        uint32_t b0, uint32_t b1) {
  asm volatile(
      "mma.sync.aligned.m16n8k16.row.col.f32.f16.f16.f32 "
      "{%0,%1,%2,%3}, {%4,%5,%6,%7}, {%8,%9}, {%0,%1,%2,%3};"
      : "+f"(c[0]), "+f"(c[1]), "+f"(c[2]), "+f"(c[3])
      : "r"(a[0]), "r"(a[1]), "r"(a[2]), "r"(a[3]), "r"(b0), "r"(b1));
}

__device__ __forceinline__ void ldmatrix_x4_trans(uint32_t& r0, uint32_t& r1,
                                                  uint32_t& r2, uint32_t& r3,
                                                  uint32_t addr) {
  asm volatile(
      "ldmatrix.sync.aligned.m8n8.x4.trans.shared.b16 {%0,%1,%2,%3}, [%4];"
      : "=r"(r0), "=r"(r1), "=r"(r2), "=r"(r3)
      : "r"(addr));
}

// ======================= kernel 0: pack mask into bits (transposed) ==========
__global__ void __launch_bounds__(256) maskbits_kernel(const int* __restrict__ mask) {
  int w = blockIdx.x * 8 + (threadIdx.x >> 5);
  int lane = threadIdx.x & 31;
  int m = mask[(size_t)w * 32 + lane];
  unsigned bits = __ballot_sync(0xffffffffu, m != 0);
  if (lane == 0) g_mbits[(size_t)(w & 63) * NSEQ + (w >> 6)] = bits;
}

// ======================= kernel 1: projections (tf32, k-chunked, 2/SM) =======
#define GST 68
__global__ void __launch_bounds__(256) proj_tc_kernel(
    const float* __restrict__ q, const float* __restrict__ k,
    const float* __restrict__ v, const float* __restrict__ Qw,
    const float* __restrict__ Kw, const float* __restrict__ Vw) {
  extern __shared__ float sm[];
  uint32_t* Xs = reinterpret_cast<uint32_t*>(sm);
  uint32_t* Ws = reinterpret_cast<uint32_t*>(sm) + 128 * GST;

  const int which = blockIdx.z;
  const float* A = (which == 0) ? q : (which == 1) ? k : v;
  const float* W = (which == 0) ? Qw : (which == 1) ? Kw : Vw;
  const int h = blockIdx.y;
  const int n0 = blockIdx.x * 128;
  const int tid = threadIdx.x;
  const int wid = tid >> 5;
  const int lane = tid & 31;
  const int qr = lane >> 2, qc = lane & 3;
  const int wm = (wid & 3) * 32;
  const int wn = (wid >> 2) * 64;

  float O[2][8][4];
#pragma unroll
  for (int mt = 0; mt < 2; mt++)
#pragma unroll
    for (int nt = 0; nt < 8; nt++)
#pragma unroll
      for (int e = 0; e < 4; e++) O[mt][nt][e] = 0.f;

  const float* Wh = W + (size_t)h * DIMD * DIMD;

  for (int kc = 0; kc < 2; kc++) {
    const int kb = kc * 64;
    __syncthreads();
    for (int idx = tid; idx < 128 * 16; idx += 256) {
      int r = idx >> 4, c4 = (idx & 15) << 2;
      float4 t = *reinterpret_cast<const float4*>(A + (size_t)(n0 + r) * DIMD + kb + c4);
      uint4 u = make_uint4(f2tf(t.x), f2tf(t.y), f2tf(t.z), f2tf(t.w));
      *reinterpret_cast<uint4*>(Xs + r * GST + c4) = u;
    }
    for (int idx = tid; idx < 128 * 16; idx += 256) {
      int e = idx & 127, d4 = (idx >> 7) << 2;
      uint4 u = make_uint4(f2tf(Wh[(size_t)(kb + d4 + 0) * DIMD + e]),
                           f2tf(Wh[(size_t)(kb + d4 + 1) * DIMD + e]),
                           f2tf(Wh[(size_t)(kb + d4 + 2) * DIMD + e]),
                           f2tf(Wh[(size_t)(kb + d4 + 3) * DIMD + e]));
      *reinterpret_cast<uint4*>(Ws + e * GST + d4) = u;
    }
    __syncthreads();

#pragma unroll
    for (int k0 = 0; k0 < 64; k0 += 8) {
      uint32_t Af[2][4];
#pragma unroll
      for (int mt = 0; mt < 2; mt++) {
        const uint32_t* ab = Xs + (wm + mt * 16 + qr) * GST + k0 + qc;
        Af[mt][0] = ab[0];
        Af[mt][1] = ab[8 * GST];
        Af[mt][2] = ab[4];
        Af[mt][3] = ab[8 * GST + 4];
      }
#pragma unroll
      for (int nt = 0; nt < 8; nt++) {
        const uint32_t* bb = Ws + (wn + nt * 8 + qr) * GST + k0 + qc;
        uint32_t b0 = bb[0], b1 = bb[4];
        mma_tf32(O[0][nt], Af[0], b0, b1);
        mma_tf32(O[1][nt], Af[1], b0, b1);
      }
    }
  }

  uint32_t* Cb2 = (which == 0 ? g_qp2 : which == 1 ? g_kp2 : g_vp2) +
                  ((size_t)h * NSEQ + n0) * 64;
#pragma unroll
  for (int mt = 0; mt < 2; mt++) {
#pragma unroll
    for (int nt = 0; nt < 8; nt++) {
      const int row0 = wm + mt * 16 + qr;
      const int cu = (wn + nt * 8) / 2 + qc;
      const float* o = O[mt][nt];
      Cb2[(size_t)row0 * 64 + cu] = f2h2(o[0], o[1]);
      Cb2[(size_t)(row0 + 8) * 64 + cu] = f2h2(o[2], o[3]);
    }
  }
}

// ======================= kernel 2: attention BM=64, 2 blocks/SM ==============
// 512 blocks (32 i-tiles x 16 heads), 256 threads / 8 warps, warp grid 2m x 4n.
// smem u32 words: K 64x68, Q 128x68, P 64x68, V 128x68, L 256.
#define ATW 68
#define AT_K 0
#define AT_Q 4352
#define AT_PP 13056
#define AT_V 17408
#define AT_L 26112
#define ATTN_SMEM_BYTES ((26112 + 256) * 4)

__global__ void __launch_bounds__(256, 2) attn_mma_kernel() {
  extern __shared__ uint32_t smu[];
  uint32_t* Ks2 = smu + AT_K;
  uint32_t* Qs2 = smu + AT_Q;
  uint32_t* Ps2 = smu + AT_PP;
  uint32_t* Vs2 = smu + AT_V;
  float* l_sh = reinterpret_cast<float*>(smu + AT_L);  // [4][64]

  const int tid = threadIdx.x;
  const int wid = tid >> 5;
  const int lane = tid & 31;
  const int qr = lane >> 2;
  const int qc = lane & 3;
  const int wm = (wid & 1) * 32;   // 2 m-warps
  const int wn = (wid >> 1) * 32;  // 4 n-warps

  const int h = blockIdx.y;
  const int i0 = blockIdx.x * 64;

  const uint32_t* kp2 = g_kp2 + (size_t)h * NSEQ * 64;
  const uint32_t* qp2 = g_qp2 + (size_t)h * NSEQ * 64;
  const uint32_t* vp2 = g_vp2 + (size_t)h * NSEQ * 64;

  // K tile (persistent, 64 rows)
#pragma unroll
  for (int p = 0; p < 4; p++) {
    int idx = tid + p * 256;
    int r = idx >> 4, c4 = (idx & 15) << 2;
    uint4 t = *reinterpret_cast<const uint4*>(kp2 + (size_t)(i0 + r) * 64 + c4);
    *reinterpret_cast<uint4*>(Ks2 + r * ATW + c4) = t;
  }

  // prefetch Q tile 0 (128 rows -> 8 uint4/thread)
  uint4 qpre[8];
#pragma unroll
  for (int p = 0; p < 8; p++) {
    int idx = tid + p * 256;
    int r = idx >> 4, c4 = (idx & 15) << 2;
    qpre[p] = *reinterpret_cast<const uint4*>(qp2 + (size_t)r * 64 + c4);
  }

  const int lg = lane >> 3;
  const int vrow0 = (lane & 7) + ((lg & 1) << 3);
  const int vn0 = (wn >> 1) + ((lg >> 1) << 2);
  const uint32_t vbase = smem_u32(Vs2);

  float O[2][4][4];
#pragma unroll
  for (int mt = 0; mt < 2; mt++)
#pragma unroll
    for (int nt = 0; nt < 4; nt++)
#pragma unroll
      for (int e = 0; e < 4; e++) O[mt][nt][e] = 0.f;
  float L[4] = {0.f, 0.f, 0.f, 0.f};

  const int row_rel[4] = {qr, qr + 8, qr + 16, qr + 24};

  for (int jt = 0; jt < NSEQ / 128; jt++) {
    const int j0 = jt * 128;
    __syncthreads();  // prev PV done reading Ps2/Vs2

    // store prefetched Q; LDG+STS V (both f16 direct)
#pragma unroll
    for (int p = 0; p < 8; p++) {
      int idx = tid + p * 256;
      int r = idx >> 4, c4 = (idx & 15) << 2;
      *reinterpret_cast<uint4*>(Qs2 + r * ATW + c4) = qpre[p];
      uint4 tv = *reinterpret_cast<const uint4*>(vp2 + (size_t)(j0 + r) * 64 + c4);
      *reinterpret_cast<uint4*>(Vs2 + r * ATW + c4) = tv;
    }
    if (jt < NSEQ / 128 - 1) {
      const int jn = j0 + 128;
#pragma unroll
      for (int p = 0; p < 8; p++) {
        int idx = tid + p * 256;
        int r = idx >> 4, c4 = (idx & 15) << 2;
        qpre[p] = *reinterpret_cast<const uint4*>(qp2 + (size_t)(jn + r) * 64 + c4);
      }
    }
    __syncthreads();

    // ---- S = K · Q^T  (warp 32m x 32n)
    float S[2][4][4];
#pragma unroll
    for (int mt = 0; mt < 2; mt++)
#pragma unroll
      for (int nt = 0; nt < 4; nt++)
#pragma unroll
        for (int e = 0; e < 4; e++) S[mt][nt][e] = 0.f;

#pragma unroll
    for (int ks = 0; ks < 8; ks++) {
      const int k8 = ks * 8;
      uint32_t A[2][4];
#pragma unroll
      for (int mt = 0; mt < 2; mt++) {
        const uint32_t* ab = Ks2 + (wm + mt * 16 + qr) * ATW + k8 + qc;
        A[mt][0] = ab[0];
        A[mt][1] = ab[8 * ATW];
        A[mt][2] = ab[4];
        A[mt][3] = ab[8 * ATW + 4];
      }
#pragma unroll
      for (int nt = 0; nt < 4; nt++) {
        const uint32_t* bb = Qs2 + (wn + nt * 8 + qr) * ATW + k8 + qc;
        uint32_t b0 = bb[0], b1 = bb[4];
        mma_f16(S[0][nt], A[0], b0, b1);
        mma_f16(S[1][nt], A[1], b0, b1);
      }
    }

    // ---- masked exp (transposed mask: coalesced)
    const unsigned* mb = g_mbits + (size_t)((j0 + wn) >> 5) * NSEQ + i0 + wm;
    unsigned mw[4];
#pragma unroll
    for (int r = 0; r < 4; r++) mw[r] = mb[row_rel[r]];

    float lacc[4] = {0.f, 0.f, 0.f, 0.f};
#pragma unroll
    for (int mt = 0; mt < 2; mt++) {
#pragma unroll
      for (int nt = 0; nt < 4; nt++) {
        const int b0 = nt * 8 + 2 * qc;
        const unsigned w0 = mw[mt * 2], w1 = mw[mt * 2 + 1];
        float* s = S[mt][nt];
        float p0 = ((w0 >> b0) & 1u) ? exp2f(s[0] * C2) : 0.f;
        float p1 = ((w0 >> (b0 + 1)) & 1u) ? exp2f(s[1] * C2) : 0.f;
        float p2 = ((w1 >> b0) & 1u) ? exp2f(s[2] * C2) : 0.f;
        float p3 = ((w1 >> (b0 + 1)) & 1u) ? exp2f(s[3] * C2) : 0.f;
        s[0] = p0; s[1] = p1; s[2] = p2; s[3] = p3;
        lacc[mt * 2] += p0 + p1;
        lacc[mt * 2 + 1] += p2 + p3;
      }
    }
#pragma unroll
    for (int r = 0; r < 4; r++) {
      float v = lacc[r];
      v += __shfl_xor_sync(0xffffffffu, v, 1);
      v += __shfl_xor_sync(0xffffffffu, v, 2);
      L[r] += v;
    }

    // ---- P -> smem as f16x2 (own buffer)
#pragma unroll
    for (int mt = 0; mt < 2; mt++) {
#pragma unroll
      for (int nt = 0; nt < 4; nt++) {
        const int row0 = wm + mt * 16 + qr;
        const int cu = (wn >> 1) + nt * 4 + qc;
        const float* s = S[mt][nt];
        Ps2[row0 * ATW + cu] = f2h2(s[0], s[1]);
        Ps2[(row0 + 8) * ATW + cu] = f2h2(s[2], s[3]);
      }
    }
    __syncthreads();

    // ---- O += P · V
    uint32_t vaddr0 = vbase + (uint32_t)(vrow0 * ATW + vn0) * 4u;
    uint32_t vaddr1 = vaddr0 + 32u;
#pragma unroll
    for (int ks = 0; ks < 8; ks++) {
      const int k8 = ks * 8;
      uint32_t A[2][4];
#pragma unroll
      for (int mt = 0; mt < 2; mt++) {
        const uint32_t* ab = Ps2 + (wm + mt * 16 + qr) * ATW + k8 + qc;
        A[mt][0] = ab[0];
        A[mt][1] = ab[8 * ATW];
        A[mt][2] = ab[4];
        A[mt][3] = ab[8 * ATW + 4];
      }
      uint32_t b0, b1, b2, b3;
      ldmatrix_x4_trans(b0, b1, b2, b3, vaddr0);
      mma_f16(O[0][0], A[0], b0, b1);
      mma_f16(O[1][0], A[1], b0, b1);
      mma_f16(O[0][1], A[0], b2, b3);
      mma_f16(O[1][1], A[1], b2, b3);
      ldmatrix_x4_trans(b0, b1, b2, b3, vaddr1);
      mma_f16(O[0][2], A[0], b0, b1);
      mma_f16(O[1][2], A[1], b0, b1);
      mma_f16(O[0][3], A[0], b2, b3);
      mma_f16(O[1][3], A[1], b2, b3);
      vaddr0 += 16u * ATW * 4u;
      vaddr1 += 16u * ATW * 4u;
    }
  }

  // combine row sums across the 4 n-warps
  if (qc == 0) {
#pragma unroll
    for (int r = 0; r < 4; r++)
      l_sh[(wid >> 1) * 64 + wm + row_rel[r]] = L[r];
  }
  __syncthreads();
  float linv[4];
#pragma unroll
  for (int r = 0; r < 4; r++) {
    int row = wm + row_rel[r];
    linv[r] = 1.f / (l_sh[row] + l_sh[64 + row] + l_sh[128 + row] + l_sh[192 + row]);
  }

#pragma unroll
  for (int mt = 0; mt < 2; mt++) {
#pragma unroll
    for (int nt = 0; nt < 4; nt++) {
      const int row0 = wm + mt * 16 + qr;
      const int col = h * DIMD + wn + nt * 8 + 2 * qc;
      const float* o = O[mt][nt];
      float2 a = make_float2(o[0] * linv[mt * 2], o[1] * linv[mt * 2]);
      float2 b = make_float2(o[2] * linv[mt * 2 + 1], o[3] * linv[mt * 2 + 1]);
      *reinterpret_cast<float2*>(g_ctx + (size_t)(i0 + row0) * (HEADS * DIMD) + col) = a;
      *reinterpret_cast<float2*>(g_ctx + (size_t)(i0 + row0 + 8) * (HEADS * DIMD) + col) = b;
    }
  }
}

// ======================= kernel 3: out (tf32, split-K 16, 2/SM) ==============
__global__ void __launch_bounds__(256) out_tc_kernel(const float* __restrict__ last) {
  extern __shared__ float sm[];
  uint32_t* Xs = reinterpret_cast<uint32_t*>(sm);
  uint32_t* Bt = reinterpret_cast<uint32_t*>(sm) + 128 * GST;

  const int m0 = blockIdx.x * 128;
  const int kc = blockIdx.y;
  const int tid = threadIdx.x;
  const int wid = tid >> 5;
  const int lane = tid & 31;
  const int qr = lane >> 2, qc = lane & 3;
  const int wm = (wid & 3) * 32;
  const int wn = (wid >> 2) * 64;

  float O[2][8][4];
#pragma unroll
  for (int mt = 0; mt < 2; mt++)
#pragma unroll
    for (int nt = 0; nt < 8; nt++)
#pragma unroll
      for (int e = 0; e < 4; e++) O[mt][nt][e] = 0.f;

  for (int ks = 0; ks < 2; ks++) {
    const int kb = kc * 128 + ks * 64;
    __syncthreads();
    for (int idx = tid; idx < 128 * 16; idx += 256) {
      int r = idx >> 4, c4 = (idx & 15) << 2;
      float4 t = *reinterpret_cast<const float4*>(
          g_ctx + (size_t)(m0 + r) * (HEADS * DIMD) + kb + c4);
      uint4 u = make_uint4(f2tf(t.x), f2tf(t.y), f2tf(t.z), f2tf(t.w));
      *reinterpret_cast<uint4*>(Xs + r * GST + c4) = u;
    }
    for (int idx = tid; idx < 128 * 16; idx += 256) {
      int e = idx & 127, k4 = (idx >> 7) << 2;
      uint4 u = make_uint4(f2tf(last[(size_t)(kb + k4 + 0) * DIMD + e]),
                           f2tf(last[(size_t)(kb + k4 + 1) * DIMD + e]),
                           f2tf(last[(size_t)(kb + k4 + 2) * DIMD + e]),
                           f2tf(last[(size_t)(kb + k4 + 3) * DIMD + e]));
      *reinterpret_cast<uint4*>(Bt + e * GST + k4) = u;
    }
    __syncthreads();

#pragma unroll
    for (int k0 = 0; k0 < 64; k0 += 8) {
      uint32_t Af[2][4];
#pragma unroll
      for (int mt = 0; mt < 2; mt++) {
        const uint32_t* ab = Xs + (wm + mt * 16 + qr) * GST + k0 + qc;
        Af[mt][0] = ab[0];
        Af[mt][1] = ab[8 * GST];
        Af[mt][2] = ab[4];
        Af[mt][3] = ab[8 * GST + 4];
      }
#pragma unroll
      for (int nt = 0; nt < 8; nt++) {
        const uint32_t* bb = Bt + (wn + nt * 8 + qr) * GST + k0 + qc;
        uint32_t b0 = bb[0], b1 = bb[4];
        mma_tf32(O[0][nt], Af[0], b0, b1);
        mma_tf32(O[1][nt], Af[1], b0, b1);
      }
    }
  }

  float* Pb = g_part + (size_t)kc * NSEQ * DIMD + (size_t)m0 * DIMD;
#pragma unroll
  for (int mt = 0; mt < 2; mt++) {
#pragma unroll
    for (int nt = 0; nt < 8; nt++) {
      const int row0 = wm + mt * 16 + qr;
      const int col = wn + nt * 8 + 2 * qc;
      const float* o = O[mt][nt];
      *reinterpret_cast<float2*>(Pb + (size_t)row0 * DIMD + col) = make_float2(o[0], o[1]);
      *reinterpret_cast<float2*>(Pb + (size_t)(row0 + 8) * DIMD + col) = make_float2(o[2], o[3]);
    }
  }
}

__global__ void __launch_bounds__(256) reduce_kernel(float* __restrict__ out) {
  int i = blockIdx.x * 256 + threadIdx.x;
  const float4* p = reinterpret_cast<const float4*>(g_part);
  float4 a = p[i];
#pragma unroll
  for (int kc = 1; kc < KSPLIT; kc++) {
    float4 b = p[(size_t)kc * (NSEQ * DIMD / 4) + i];
    a.x += b.x; a.y += b.y; a.z += b.z; a.w += b.w;
  }
  reinterpret_cast<float4*>(out)[i] = a;
}

// =====================================================================
extern "C" void kernel_launch(void* const* d_in, const int* in_sizes, int n_in,
                              void* d_out, int out_size) {
  int mi = -1;
  for (int i = 0; i < n_in; i++)
    if (in_sizes[i] == NSEQ * NSEQ) { mi = i; break; }
  if (mi < 0) mi = 3;

  const void* p[7];
  int np = 0;
  for (int i = 0; i < n_in && np < 7; i++) {
    if (i == mi) continue;
    p[np++] = d_in[i];
  }
  const float* q = (const float*)p[0];
  const float* k = (const float*)p[1];
  const float* v = (const float*)p[2];
  const float* Qw = (const float*)p[3];
  const float* Kw = (const float*)p[4];
  const float* Vw = (const float*)p[5];
  const float* last = (const float*)p[6];
  const int* mask = (const int*)d_in[mi];
  float* out = (float*)d_out;

  const int GEMM_SMEM = 2 * 128 * GST * 4;  // 69,632 B

  cudaFuncSetAttribute(proj_tc_kernel, cudaFuncAttributeMaxDynamicSharedMemorySize, GEMM_SMEM);
  cudaFuncSetAttribute(out_tc_kernel, cudaFuncAttributeMaxDynamicSharedMemorySize, GEMM_SMEM);
  cudaFuncSetAttribute(attn_mma_kernel, cudaFuncAttributeMaxDynamicSharedMemorySize,
                       ATTN_SMEM_BYTES);

  maskbits_kernel<<<NSEQ * (NSEQ / 32) / 8, 256>>>(mask);
  proj_tc_kernel<<<dim3(NSEQ / 128, HEADS, 3), 256, GEMM_SMEM>>>(q, k, v, Qw, Kw, Vw);
  attn_mma_kernel<<<dim3(NSEQ / 64, HEADS), 256, ATTN_SMEM_BYTES>>>();
  out_tc_kernel<<<dim3(NSEQ / 128, KSPLIT), 256, GEMM_SMEM>>>(last);
  reduce_kernel<<<NSEQ * DIMD / 4 / 256, 256>>>(out);
}

// round 10
// speedup vs baseline: 1.1614x; 1.1614x over previous
#include <cuda_runtime.h>
#include <cstdint>

#define HEADS 16
#define DIMD 128
#define NSEQ 2048
/* exp(x*INV_SQRT_N) == exp2(x*C2) */
#define C2 0.0318793576f
#define KSPLIT 16

// ---------------- scratch (static device globals; no allocations) ----------------
__device__ __align__(16) uint32_t g_qp2[HEADS * NSEQ * 64];  // f16x2 packed
__device__ __align__(16) uint32_t g_kp2[HEADS * NSEQ * 64];  // f16x2 packed
__device__ __align__(16) uint32_t g_vp2[HEADS * NSEQ * 64];  // f16x2 packed
__device__ __align__(16) float g_ctx[NSEQ * HEADS * DIMD];
__device__ __align__(16) float g_part[KSPLIT * NSEQ * DIMD];
__device__ __align__(16) unsigned g_mbits[(NSEQ / 32) * NSEQ];  // [word][row]

// ---------------- helpers ----------------
__device__ __forceinline__ uint32_t f2tf(float x) {
  uint32_t r;
  asm("cvt.rna.tf32.f32 %0, %1;" : "=r"(r) : "f"(x));
  return r;
}
__device__ __forceinline__ uint32_t f2h2(float lo, float hi) {
  uint32_t r;
  asm("cvt.rn.f16x2.f32 %0, %1, %2;" : "=r"(r) : "f"(hi), "f"(lo));
  return r;
}
__device__ __forceinline__ uint32_t smem_u32(const void* p) {
  uint32_t a;
  asm("{ .reg .u64 t; cvta.to.shared.u64 t, %1; cvt.u32.u64 %0, t; }" : "=r"(a) : "l"(p));
  return a;
}

#define CP_ASYNC16(saddr, gptr)                                                 \
  asm volatile("cp.async.cg.shared.global [%0], [%1], 16;" ::"r"(saddr),        \
               "l"(gptr) : "memory")
#define CP_COMMIT() asm volatile("cp.async.commit_group;" ::: "memory")
#define CP_WAIT1() asm volatile("cp.async.wait_group 1;" ::: "memory")
#define CP_WAIT0() asm volatile("cp.async.wait_group 0;" ::: "memory")

__device__ __forceinline__ void mma_tf32(float c[4], const uint32_t a[4],
                                         uint32_t b0, uint32_t b1) {
  asm volatile(
      "mma.sync.aligned.m16n8k8.row.col.f32.tf32.tf32.f32 "
      "{%0,%1,%2,%3}, {%4,%5,%6,%7}, {%8,%9}, {%0,%1,%2,%3};"
      : "+f"(c[0]), "+f"(c[1]), "+f"(c[2]), "+f"(c[3])
      : "r"(a[0]), "r"(a[1]), "r"(a[2]), "r"(a[3]), "r"(b0), "r"(b1));
}

__device__ __forceinline__ void mma_f16(float c[4], const uint32_t a[4],
                                        uint32_t b0, uint32_t b1) {
  asm volatile(
      "mma.sync.aligned.m16n8k16.row.col.f32.f16.f16.f32 "
      "{%0,%1,%2,%3}, {%4,%5,%6,%7}, {%8,%9}, {%0,%1,%2,%3};"
      : "+f"(c[0]), "+f"(c[1]), "+f"(c[2]), "+f"(c[3])
      : "r"(a[0]), "r"(a[1]), "r"(a[2]), "r"(a[3]), "r"(b0), "r"(b1));
}

__device__ __forceinline__ void ldmatrix_x4_trans(uint32_t& r0, uint32_t& r1,
                                                  uint32_t& r2, uint32_t& r3,
                                                  uint32_t addr) {
  asm volatile(
      "ldmatrix.sync.aligned.m8n8.x4.trans.shared.b16 {%0,%1,%2,%3}, [%4];"
      : "=r"(r0), "=r"(r1), "=r"(r2), "=r"(r3)
      : "r"(addr));
}

// ======================= kernel 0: pack mask into bits (transposed) ==========
__global__ void __launch_bounds__(256) maskbits_kernel(const int* __restrict__ mask) {
  int w = blockIdx.x * 8 + (threadIdx.x >> 5);
  int lane = threadIdx.x & 31;
  int m = mask[(size_t)w * 32 + lane];
  unsigned bits = __ballot_sync(0xffffffffu, m != 0);
  if (lane == 0) g_mbits[(size_t)(w & 63) * NSEQ + (w >> 6)] = bits;
}

// ======================= kernel 1: projections (tf32, k-chunked, 2/SM) =======
#define GST 68
__global__ void __launch_bounds__(256) proj_tc_kernel(
    const float* __restrict__ q, const float* __restrict__ k,
    const float* __restrict__ v, const float* __restrict__ Qw,
    const float* __restrict__ Kw, const float* __restrict__ Vw) {
  extern __shared__ float sm[];
  uint32_t* Xs = reinterpret_cast<uint32_t*>(sm);
  uint32_t* Ws = reinterpret_cast<uint32_t*>(sm) + 128 * GST;

  const int which = blockIdx.z;
  const float* A = (which == 0) ? q : (which == 1) ? k : v;
  const float* W = (which == 0) ? Qw : (which == 1) ? Kw : Vw;
  const int h = blockIdx.y;
  const int n0 = blockIdx.x * 128;
  const int tid = threadIdx.x;
  const int wid = tid >> 5;
  const int lane = tid & 31;
  const int qr = lane >> 2, qc = lane & 3;
  const int wm = (wid & 3) * 32;
  const int wn = (wid >> 2) * 64;

  float O[2][8][4];
#pragma unroll
  for (int mt = 0; mt < 2; mt++)
#pragma unroll
    for (int nt = 0; nt < 8; nt++)
#pragma unroll
      for (int e = 0; e < 4; e++) O[mt][nt][e] = 0.f;

  const float* Wh = W + (size_t)h * DIMD * DIMD;

  for (int kc = 0; kc < 2; kc++) {
    const int kb = kc * 64;
    __syncthreads();
    for (int idx = tid; idx < 128 * 16; idx += 256) {
      int r = idx >> 4, c4 = (idx & 15) << 2;
      float4 t = *reinterpret_cast<const float4*>(A + (size_t)(n0 + r) * DIMD + kb + c4);
      uint4 u = make_uint4(f2tf(t.x), f2tf(t.y), f2tf(t.z), f2tf(t.w));
      *reinterpret_cast<uint4*>(Xs + r * GST + c4) = u;
    }
    for (int idx = tid; idx < 128 * 16; idx += 256) {
      int e = idx & 127, d4 = (idx >> 7) << 2;
      uint4 u = make_uint4(f2tf(Wh[(size_t)(kb + d4 + 0) * DIMD + e]),
                           f2tf(Wh[(size_t)(kb + d4 + 1) * DIMD + e]),
                           f2tf(Wh[(size_t)(kb + d4 + 2) * DIMD + e]),
                           f2tf(Wh[(size_t)(kb + d4 + 3) * DIMD + e]));
      *reinterpret_cast<uint4*>(Ws + e * GST + d4) = u;
    }
    __syncthreads();

#pragma unroll
    for (int k0 = 0; k0 < 64; k0 += 8) {
      uint32_t Af[2][4];
#pragma unroll
      for (int mt = 0; mt < 2; mt++) {
        const uint32_t* ab = Xs + (wm + mt * 16 + qr) * GST + k0 + qc;
        Af[mt][0] = ab[0];
        Af[mt][1] = ab[8 * GST];
        Af[mt][2] = ab[4];
        Af[mt][3] = ab[8 * GST + 4];
      }
#pragma unroll
      for (int nt = 0; nt < 8; nt++) {
        const uint32_t* bb = Ws + (wn + nt * 8 + qr) * GST + k0 + qc;
        uint32_t b0 = bb[0], b1 = bb[4];
        mma_tf32(O[0][nt], Af[0], b0, b1);
        mma_tf32(O[1][nt], Af[1], b0, b1);
      }
    }
  }

  uint32_t* Cb2 = (which == 0 ? g_qp2 : which == 1 ? g_kp2 : g_vp2) +
                  ((size_t)h * NSEQ + n0) * 64;
#pragma unroll
  for (int mt = 0; mt < 2; mt++) {
#pragma unroll
    for (int nt = 0; nt < 8; nt++) {
      const int row0 = wm + mt * 16 + qr;
      const int cu = (wn + nt * 8) / 2 + qc;
      const float* o = O[mt][nt];
      Cb2[(size_t)row0 * 64 + cu] = f2h2(o[0], o[1]);
      Cb2[(size_t)(row0 + 8) * 64 + cu] = f2h2(o[2], o[3]);
    }
  }
}

// ======================= kernel 2: attention BM=128, cp.async double-buffer ==
// 256 blocks (16 i-tiles x 16 heads), 512 threads / 16 warps, 4m x 4n.
// smem u32 words: K 8704 @0, Q0 @8704, Q1 @17408, V0 @26112, V1 @34816,
//                 P @43520, L(512 f32) @52224.  Total 210,944 B.
#define ATW 68
#define AT_Q0 8704
#define AT_Q1 17408
#define AT_V0 26112
#define AT_V1 34816
#define AT_PP 43520
#define AT_L 52224
#define ATTN_SMEM_BYTES ((52224 + 512) * 4)

__global__ void __launch_bounds__(512) attn_mma_kernel() {
  extern __shared__ uint32_t smu[];
  const uint32_t sbase = smem_u32(smu);
  uint32_t* Ks2 = smu;
  uint32_t* Ps2 = smu + AT_PP;
  float* l_sh = reinterpret_cast<float*>(smu + AT_L);

  const int tid = threadIdx.x;
  const int wid = tid >> 5;
  const int lane = tid & 31;
  const int qr = lane >> 2;
  const int qc = lane & 3;
  const int wm = (wid & 3) * 32;
  const int wn = (wid >> 2) * 32;

  const int h = blockIdx.y;
  const int i0 = blockIdx.x * 128;

  const uint32_t* kp2 = g_kp2 + (size_t)h * NSEQ * 64;
  const uint32_t* qp2 = g_qp2 + (size_t)h * NSEQ * 64;
  const uint32_t* vp2 = g_vp2 + (size_t)h * NSEQ * 64;

  // per-thread copy coordinates (4 chunks of 16B per tile per tensor)
  const int cr = tid >> 4;              // row 0..31 (+32 per chunk)
  const int cc4 = (tid & 15) << 2;      // u32 col

  // K tile (persistent), synchronous copy once
#pragma unroll
  for (int p = 0; p < 4; p++) {
    int r = cr + p * 32;
    uint4 t = *reinterpret_cast<const uint4*>(kp2 + (size_t)(i0 + r) * 64 + cc4);
    *reinterpret_cast<uint4*>(Ks2 + r * ATW + cc4) = t;
  }

  // prologue: cp.async tile 0 into buffer 0
#pragma unroll
  for (int p = 0; p < 4; p++) {
    int r = cr + p * 32;
    uint32_t so = (uint32_t)(r * ATW + cc4) * 4u;
    CP_ASYNC16(sbase + AT_Q0 * 4u + so, qp2 + (size_t)r * 64 + cc4);
    CP_ASYNC16(sbase + AT_V0 * 4u + so, vp2 + (size_t)r * 64 + cc4);
  }
  CP_COMMIT();

  const int lg = lane >> 3;
  const int vrow0 = (lane & 7) + ((lg & 1) << 3);
  const int vn0 = (wn >> 1) + ((lg >> 1) << 2);

  float O[2][4][4];
#pragma unroll
  for (int mt = 0; mt < 2; mt++)
#pragma unroll
    for (int nt = 0; nt < 4; nt++)
#pragma unroll
      for (int e = 0; e < 4; e++) O[mt][nt][e] = 0.f;
  float L[4] = {0.f, 0.f, 0.f, 0.f};

  const int row_rel[4] = {qr, qr + 8, qr + 16, qr + 24};

  for (int jt = 0; jt < NSEQ / 128; jt++) {
    const int j0 = jt * 128;
    __syncthreads();  // (A) all warps done with prev PV -> next buffer & P free

    if (jt < NSEQ / 128 - 1) {
      const int jn = j0 + 128;
      const uint32_t qoff = ((jt + 1) & 1) ? AT_Q1 : AT_Q0;
      const uint32_t voff = ((jt + 1) & 1) ? AT_V1 : AT_V0;
#pragma unroll
      for (int p = 0; p < 4; p++) {
        int r = cr + p * 32;
        uint32_t so = (uint32_t)(r * ATW + cc4) * 4u;
        CP_ASYNC16(sbase + qoff * 4u + so, qp2 + (size_t)(jn + r) * 64 + cc4);
        CP_ASYNC16(sbase + voff * 4u + so, vp2 + (size_t)(jn + r) * 64 + cc4);
      }
      CP_COMMIT();
      CP_WAIT1();
    } else {
      CP_WAIT0();
    }
    __syncthreads();  // (B) tile jt resident & visible

    const uint32_t* Qs2 = smu + ((jt & 1) ? AT_Q1 : AT_Q0);
    const uint32_t vbase = sbase + ((jt & 1) ? AT_V1 : AT_V0) * 4u;

    // ---- S = K · Q^T  (warp 32m x 32n)
    float S[2][4][4];
#pragma unroll
    for (int mt = 0; mt < 2; mt++)
#pragma unroll
      for (int nt = 0; nt < 4; nt++)
#pragma unroll
        for (int e = 0; e < 4; e++) S[mt][nt][e] = 0.f;

#pragma unroll
    for (int ks = 0; ks < 8; ks++) {
      const int k8 = ks * 8;
      uint32_t A[2][4];
#pragma unroll
      for (int mt = 0; mt < 2; mt++) {
        const uint32_t* ab = Ks2 + (wm + mt * 16 + qr) * ATW + k8 + qc;
        A[mt][0] = ab[0];
        A[mt][1] = ab[8 * ATW];
        A[mt][2] = ab[4];
        A[mt][3] = ab[8 * ATW + 4];
      }
#pragma unroll
      for (int nt = 0; nt < 4; nt++) {
        const uint32_t* bb = Qs2 + (wn + nt * 8 + qr) * ATW + k8 + qc;
        uint32_t b0 = bb[0], b1 = bb[4];
        mma_f16(S[0][nt], A[0], b0, b1);
        mma_f16(S[1][nt], A[1], b0, b1);
      }
    }

    // ---- masked exp (transposed mask: coalesced)
    const unsigned* mb = g_mbits + (size_t)((j0 + wn) >> 5) * NSEQ + i0 + wm;
    unsigned mw[4];
#pragma unroll
    for (int r = 0; r < 4; r++) mw[r] = mb[row_rel[r]];

    float lacc[4] = {0.f, 0.f, 0.f, 0.f};
#pragma unroll
    for (int mt = 0; mt < 2; mt++) {
#pragma unroll
      for (int nt = 0; nt < 4; nt++) {
        const int b0 = nt * 8 + 2 * qc;
        const unsigned w0 = mw[mt * 2], w1 = mw[mt * 2 + 1];
        float* s = S[mt][nt];
        float p0 = ((w0 >> b0) & 1u) ? exp2f(s[0] * C2) : 0.f;
        float p1 = ((w0 >> (b0 + 1)) & 1u) ? exp2f(s[1] * C2) : 0.f;
        float p2 = ((w1 >> b0) & 1u) ? exp2f(s[2] * C2) : 0.f;
        float p3 = ((w1 >> (b0 + 1)) & 1u) ? exp2f(s[3] * C2) : 0.f;
        s[0] = p0; s[1] = p1; s[2] = p2; s[3] = p3;
        lacc[mt * 2] += p0 + p1;
        lacc[mt * 2 + 1] += p2 + p3;
      }
    }
#pragma unroll
    for (int r = 0; r < 4; r++) {
      float v = lacc[r];
      v += __shfl_xor_sync(0xffffffffu, v, 1);
      v += __shfl_xor_sync(0xffffffffu, v, 2);
      L[r] += v;
    }

    // ---- P -> smem as f16x2 (own buffer)
#pragma unroll
    for (int mt = 0; mt < 2; mt++) {
#pragma unroll
      for (int nt = 0; nt < 4; nt++) {
        const int row0 = wm + mt * 16 + qr;
        const int cu = (wn >> 1) + nt * 4 + qc;
        const float* s = S[mt][nt];
        Ps2[row0 * ATW + cu] = f2h2(s[0], s[1]);
        Ps2[(row0 + 8) * ATW + cu] = f2h2(s[2], s[3]);
      }
    }
    __syncthreads();  // (C) P complete

    // ---- O += P · V
    uint32_t vaddr0 = vbase + (uint32_t)(vrow0 * ATW + vn0) * 4u;
    uint32_t vaddr1 = vaddr0 + 32u;
#pragma unroll
    for (int ks = 0; ks < 8; ks++) {
      const int k8 = ks * 8;
      uint32_t A[2][4];
#pragma unroll
      for (int mt = 0; mt < 2; mt++) {
        const uint32_t* ab = Ps2 + (wm + mt * 16 + qr) * ATW + k8 + qc;
        A[mt][0] = ab[0];
        A[mt][1] = ab[8 * ATW];
        A[mt][2] = ab[4];
        A[mt][3] = ab[8 * ATW + 4];
      }
      uint32_t b0, b1, b2, b3;
      ldmatrix_x4_trans(b0, b1, b2, b3, vaddr0);
      mma_f16(O[0][0], A[0], b0, b1);
      mma_f16(O[1][0], A[1], b0, b1);
      mma_f16(O[0][1], A[0], b2, b3);
      mma_f16(O[1][1], A[1], b2, b3);
      ldmatrix_x4_trans(b0, b1, b2, b3, vaddr1);
      mma_f16(O[0][2], A[0], b0, b1);
      mma_f16(O[1][2], A[1], b0, b1);
      mma_f16(O[0][3], A[0], b2, b3);
      mma_f16(O[1][3], A[1], b2, b3);
      vaddr0 += 16u * ATW * 4u;
      vaddr1 += 16u * ATW * 4u;
    }
  }

  // combine row sums across the 4 n-warps
  if (qc == 0) {
#pragma unroll
    for (int r = 0; r < 4; r++)
      l_sh[(wid >> 2) * 128 + wm + row_rel[r]] = L[r];
  }
  __syncthreads();
  float linv[4];
#pragma unroll
  for (int r = 0; r < 4; r++) {
    int row = wm + row_rel[r];
    linv[r] = 1.f / (l_sh[row] + l_sh[128 + row] + l_sh[256 + row] + l_sh[384 + row]);
  }

#pragma unroll
  for (int mt = 0; mt < 2; mt++) {
#pragma unroll
    for (int nt = 0; nt < 4; nt++) {
      const int row0 = wm + mt * 16 + qr;
      const int col = h * DIMD + wn + nt * 8 + 2 * qc;
      const float* o = O[mt][nt];
      float2 a = make_float2(o[0] * linv[mt * 2], o[1] * linv[mt * 2]);
      float2 b = make_float2(o[2] * linv[mt * 2 + 1], o[3] * linv[mt * 2 + 1]);
      *reinterpret_cast<float2*>(g_ctx + (size_t)(i0 + row0) * (HEADS * DIMD) + col) = a;
      *reinterpret_cast<float2*>(g_ctx + (size_t)(i0 + row0 + 8) * (HEADS * DIMD) + col) = b;
    }
  }
}

// ======================= kernel 3: out (tf32, split-K 16, 2/SM) ==============
__global__ void __launch_bounds__(256) out_tc_kernel(const float* __restrict__ last) {
  extern __shared__ float sm[];
  uint32_t* Xs = reinterpret_cast<uint32_t*>(sm);
  uint32_t* Bt = reinterpret_cast<uint32_t*>(sm) + 128 * GST;

  const int m0 = blockIdx.x * 128;
  const int kc = blockIdx.y;
  const int tid = threadIdx.x;
  const int wid = tid >> 5;
  const int lane = tid & 31;
  const int qr = lane >> 2, qc = lane & 3;
  const int wm = (wid & 3) * 32;
  const int wn = (wid >> 2) * 64;

  float O[2][8][4];
#pragma unroll
  for (int mt = 0; mt < 2; mt++)
#pragma unroll
    for (int nt = 0; nt < 8; nt++)
#pragma unroll
      for (int e = 0; e < 4; e++) O[mt][nt][e] = 0.f;

  for (int ks = 0; ks < 2; ks++) {
    const int kb = kc * 128 + ks * 64;
    __syncthreads();
    for (int idx = tid; idx < 128 * 16; idx += 256) {
      int r = idx >> 4, c4 = (idx & 15) << 2;
      float4 t = *reinterpret_cast<const float4*>(
          g_ctx + (size_t)(m0 + r) * (HEADS * DIMD) + kb + c4);
      uint4 u = make_uint4(f2tf(t.x), f2tf(t.y), f2tf(t.z), f2tf(t.w));
      *reinterpret_cast<uint4*>(Xs + r * GST + c4) = u;
    }
    for (int idx = tid; idx < 128 * 16; idx += 256) {
      int e = idx & 127, k4 = (idx >> 7) << 2;
      uint4 u = make_uint4(f2tf(last[(size_t)(kb + k4 + 0) * DIMD + e]),
                           f2tf(last[(size_t)(kb + k4 + 1) * DIMD + e]),
                           f2tf(last[(size_t)(kb + k4 + 2) * DIMD + e]),
                           f2tf(last[(size_t)(kb + k4 + 3) * DIMD + e]));
      *reinterpret_cast<uint4*>(Bt + e * GST + k4) = u;
    }
    __syncthreads();

#pragma unroll
    for (int k0 = 0; k0 < 64; k0 += 8) {
      uint32_t Af[2][4];
#pragma unroll
      for (int mt = 0; mt < 2; mt++) {
        const uint32_t* ab = Xs + (wm + mt * 16 + qr) * GST + k0 + qc;
        Af[mt][0] = ab[0];
        Af[mt][1] = ab[8 * GST];
        Af[mt][2] = ab[4];
        Af[mt][3] = ab[8 * GST + 4];
      }
#pragma unroll
      for (int nt = 0; nt < 8; nt++) {
        const uint32_t* bb = Bt + (wn + nt * 8 + qr) * GST + k0 + qc;
        uint32_t b0 = bb[0], b1 = bb[4];
        mma_tf32(O[0][nt], Af[0], b0, b1);
        mma_tf32(O[1][nt], Af[1], b0, b1);
      }
    }
  }

  float* Pb = g_part + (size_t)kc * NSEQ * DIMD + (size_t)m0 * DIMD;
#pragma unroll
  for (int mt = 0; mt < 2; mt++) {
#pragma unroll
    for (int nt = 0; nt < 8; nt++) {
      const int row0 = wm + mt * 16 + qr;
      const int col = wn + nt * 8 + 2 * qc;
      const float* o = O[mt][nt];
      *reinterpret_cast<float2*>(Pb + (size_t)row0 * DIMD + col) = make_float2(o[0], o[1]);
      *reinterpret_cast<float2*>(Pb + (size_t)(row0 + 8) * DIMD + col) = make_float2(o[2], o[3]);
    }
  }
}

__global__ void __launch_bounds__(256) reduce_kernel(float* __restrict__ out) {
  int i = blockIdx.x * 256 + threadIdx.x;
  const float4* p = reinterpret_cast<const float4*>(g_part);
  float4 a = p[i];
#pragma unroll
  for (int kc = 1; kc < KSPLIT; kc++) {
    float4 b = p[(size_t)kc * (NSEQ * DIMD / 4) + i];
    a.x += b.x; a.y += b.y; a.z += b.z; a.w += b.w;
  }
  reinterpret_cast<float4*>(out)[i] = a;
}

// =====================================================================
extern "C" void kernel_launch(void* const* d_in, const int* in_sizes, int n_in,
                              void* d_out, int out_size) {
  int mi = -1;
  for (int i = 0; i < n_in; i++)
    if (in_sizes[i] == NSEQ * NSEQ) { mi = i; break; }
  if (mi < 0) mi = 3;

  const void* p[7];
  int np = 0;
  for (int i = 0; i < n_in && np < 7; i++) {
    if (i == mi) continue;
    p[np++] = d_in[i];
  }
  const float* q = (const float*)p[0];
  const float* k = (const float*)p[1];
  const float* v = (const float*)p[2];
  const float* Qw = (const float*)p[3];
  const float* Kw = (const float*)p[4];
  const float* Vw = (const float*)p[5];
  const float* last = (const float*)p[6];
  const int* mask = (const int*)d_in[mi];
  float* out = (float*)d_out;

  const int GEMM_SMEM = 2 * 128 * GST * 4;  // 69,632 B

  cudaFuncSetAttribute(proj_tc_kernel, cudaFuncAttributeMaxDynamicSharedMemorySize, GEMM_SMEM);
  cudaFuncSetAttribute(out_tc_kernel, cudaFuncAttributeMaxDynamicSharedMemorySize, GEMM_SMEM);
  cudaFuncSetAttribute(attn_mma_kernel, cudaFuncAttributeMaxDynamicSharedMemorySize,
                       ATTN_SMEM_BYTES);

  maskbits_kernel<<<NSEQ * (NSEQ / 32) / 8, 256>>>(mask);
  proj_tc_kernel<<<dim3(NSEQ / 128, HEADS, 3), 256, GEMM_SMEM>>>(q, k, v, Qw, Kw, Vw);
  attn_mma_kernel<<<dim3(NSEQ / 128, HEADS), 512, ATTN_SMEM_BYTES>>>();
  out_tc_kernel<<<dim3(NSEQ / 128, KSPLIT), 256, GEMM_SMEM>>>(last);
  reduce_kernel<<<NSEQ * DIMD / 4 / 256, 256>>>(out);
}

// round 11
// speedup vs baseline: 1.1897x; 1.0243x over previous
#include <cuda_runtime.h>
#include <cstdint>

#define HEADS 16
#define DIMD 128
#define NSEQ 2048
/* exp(x*INV_SQRT_N) == exp2(x*C2) */
#define C2 0.0318793576f
#define KSPLIT 16

// ---------------- scratch (static device globals; no allocations) ----------------
__device__ __align__(16) uint32_t g_qp2[HEADS * NSEQ * 64];   // f16x2 packed
__device__ __align__(16) uint32_t g_kp2[HEADS * NSEQ * 64];   // f16x2 packed
__device__ __align__(16) uint32_t g_vp2[HEADS * NSEQ * 64];   // f16x2 packed
__device__ __align__(16) uint32_t g_ctx2[NSEQ * 1024];        // f16x2 packed [n][h*64+du]
__device__ __align__(16) float g_part[KSPLIT * NSEQ * DIMD];
__device__ __align__(16) unsigned g_mbits[(NSEQ / 32) * NSEQ];  // [word][row]

// ---------------- helpers ----------------
__device__ __forceinline__ uint32_t f2h2(float lo, float hi) {
  uint32_t r;
  asm("cvt.rn.f16x2.f32 %0, %1, %2;" : "=r"(r) : "f"(hi), "f"(lo));
  return r;
}
__device__ __forceinline__ uint32_t smem_u32(const void* p) {
  uint32_t a;
  asm("{ .reg .u64 t; cvta.to.shared.u64 t, %1; cvt.u32.u64 %0, t; }" : "=r"(a) : "l"(p));
  return a;
}

#define CP_ASYNC16(saddr, gptr)                                                 \
  asm volatile("cp.async.cg.shared.global [%0], [%1], 16;" ::"r"(saddr),        \
               "l"(gptr) : "memory")
#define CP_COMMIT() asm volatile("cp.async.commit_group;" ::: "memory")
#define CP_WAIT1() asm volatile("cp.async.wait_group 1;" ::: "memory")
#define CP_WAIT0() asm volatile("cp.async.wait_group 0;" ::: "memory")

__device__ __forceinline__ void mma_f16(float c[4], const uint32_t a[4],
                                        uint32_t b0, uint32_t b1) {
  asm volatile(
      "mma.sync.aligned.m16n8k16.row.col.f32.f16.f16.f32 "
      "{%0,%1,%2,%3}, {%4,%5,%6,%7}, {%8,%9}, {%0,%1,%2,%3};"
      : "+f"(c[0]), "+f"(c[1]), "+f"(c[2]), "+f"(c[3])
      : "r"(a[0]), "r"(a[1]), "r"(a[2]), "r"(a[3]), "r"(b0), "r"(b1));
}

__device__ __forceinline__ void ldmatrix_x4_trans(uint32_t& r0, uint32_t& r1,
                                                  uint32_t& r2, uint32_t& r3,
                                                  uint32_t addr) {
  asm volatile(
      "ldmatrix.sync.aligned.m8n8.x4.trans.shared.b16 {%0,%1,%2,%3}, [%4];"
      : "=r"(r0), "=r"(r1), "=r"(r2), "=r"(r3)
      : "r"(addr));
}

// ======================= kernel 0: pack mask into bits (transposed) ==========
__global__ void __launch_bounds__(256) maskbits_kernel(const int* __restrict__ mask) {
  int w = blockIdx.x * 8 + (threadIdx.x >> 5);
  int lane = threadIdx.x & 31;
  int m = mask[(size_t)w * 32 + lane];
  unsigned bits = __ballot_sync(0xffffffffu, m != 0);
  if (lane == 0) g_mbits[(size_t)(w & 63) * NSEQ + (w >> 6)] = bits;
}

// ======================= kernel 1: projections (f16 tensor, one pass) =======
// Xs [128 n][64 u32 (k-packed)] st 68; Ws [128 e][64 u32] st 68 (W^T packed).
#define GW 68
__global__ void __launch_bounds__(256) proj_tc_kernel(
    const float* __restrict__ q, const float* __restrict__ k,
    const float* __restrict__ v, const float* __restrict__ Qw,
    const float* __restrict__ Kw, const float* __restrict__ Vw) {
  extern __shared__ uint32_t smg[];
  uint32_t* Xs = smg;
  uint32_t* Ws = smg + 128 * GW;

  const int which = blockIdx.z;
  const float* A = (which == 0) ? q : (which == 1) ? k : v;
  const float* W = (which == 0) ? Qw : (which == 1) ? Kw : Vw;
  const int h = blockIdx.y;
  const int n0 = blockIdx.x * 128;
  const int tid = threadIdx.x;
  const int wid = tid >> 5;
  const int lane = tid & 31;
  const int qr = lane >> 2, qc = lane & 3;
  const int wm = (wid & 3) * 32;
  const int wn = (wid >> 2) * 64;

  // X packed f16
  for (int idx = tid; idx < 128 * 32; idx += 256) {
    int r = idx >> 5, c4 = (idx & 31) << 2;
    float4 t = *reinterpret_cast<const float4*>(A + (size_t)(n0 + r) * DIMD + c4);
    *reinterpret_cast<uint2*>(Xs + r * GW + (c4 >> 1)) =
        make_uint2(f2h2(t.x, t.y), f2h2(t.z, t.w));
  }
  // W^T packed f16 (coalesced along e)
  const float* Wh = W + (size_t)h * DIMD * DIMD;
  for (int idx = tid; idx < 128 * 32; idx += 256) {
    int e = idx & 127, d4 = (idx >> 7) << 2;
    *reinterpret_cast<uint2*>(Ws + e * GW + (d4 >> 1)) = make_uint2(
        f2h2(Wh[(size_t)(d4 + 0) * DIMD + e], Wh[(size_t)(d4 + 1) * DIMD + e]),
        f2h2(Wh[(size_t)(d4 + 2) * DIMD + e], Wh[(size_t)(d4 + 3) * DIMD + e]));
  }
  __syncthreads();

  float O[2][8][4];
#pragma unroll
  for (int mt = 0; mt < 2; mt++)
#pragma unroll
    for (int nt = 0; nt < 8; nt++)
#pragma unroll
      for (int e = 0; e < 4; e++) O[mt][nt][e] = 0.f;

#pragma unroll
  for (int ks = 0; ks < 8; ks++) {
    const int k8 = ks * 8;
    uint32_t Af[2][4];
#pragma unroll
    for (int mt = 0; mt < 2; mt++) {
      const uint32_t* ab = Xs + (wm + mt * 16 + qr) * GW + k8 + qc;
      Af[mt][0] = ab[0];
      Af[mt][1] = ab[8 * GW];
      Af[mt][2] = ab[4];
      Af[mt][3] = ab[8 * GW + 4];
    }
#pragma unroll
    for (int nt = 0; nt < 8; nt++) {
      const uint32_t* bb = Ws + (wn + nt * 8 + qr) * GW + k8 + qc;
      uint32_t b0 = bb[0], b1 = bb[4];
      mma_f16(O[0][nt], Af[0], b0, b1);
      mma_f16(O[1][nt], Af[1], b0, b1);
    }
  }

  uint32_t* Cb2 = (which == 0 ? g_qp2 : which == 1 ? g_kp2 : g_vp2) +
                  ((size_t)h * NSEQ + n0) * 64;
#pragma unroll
  for (int mt = 0; mt < 2; mt++) {
#pragma unroll
    for (int nt = 0; nt < 8; nt++) {
      const int row0 = wm + mt * 16 + qr;
      const int cu = (wn + nt * 8) / 2 + qc;
      const float* o = O[mt][nt];
      Cb2[(size_t)row0 * 64 + cu] = f2h2(o[0], o[1]);
      Cb2[(size_t)(row0 + 8) * 64 + cu] = f2h2(o[2], o[3]);
    }
  }
}

// ======================= kernel 2: attention BM=128, cp.async double-buffer ==
#define ATW 68
#define AT_Q0 8704
#define AT_Q1 17408
#define AT_V0 26112
#define AT_V1 34816
#define AT_PP 43520
#define AT_L 52224
#define ATTN_SMEM_BYTES ((52224 + 512) * 4)

__global__ void __launch_bounds__(512) attn_mma_kernel() {
  extern __shared__ uint32_t smu[];
  const uint32_t sbase = smem_u32(smu);
  uint32_t* Ks2 = smu;
  uint32_t* Ps2 = smu + AT_PP;
  float* l_sh = reinterpret_cast<float*>(smu + AT_L);

  const int tid = threadIdx.x;
  const int wid = tid >> 5;
  const int lane = tid & 31;
  const int qr = lane >> 2;
  const int qc = lane & 3;
  const int wm = (wid & 3) * 32;
  const int wn = (wid >> 2) * 32;

  const int h = blockIdx.y;
  const int i0 = blockIdx.x * 128;

  const uint32_t* kp2 = g_kp2 + (size_t)h * NSEQ * 64;
  const uint32_t* qp2 = g_qp2 + (size_t)h * NSEQ * 64;
  const uint32_t* vp2 = g_vp2 + (size_t)h * NSEQ * 64;

  const int cr = tid >> 4;
  const int cc4 = (tid & 15) << 2;

  // K tile (persistent)
#pragma unroll
  for (int p = 0; p < 4; p++) {
    int r = cr + p * 32;
    uint4 t = *reinterpret_cast<const uint4*>(kp2 + (size_t)(i0 + r) * 64 + cc4);
    *reinterpret_cast<uint4*>(Ks2 + r * ATW + cc4) = t;
  }

  // prologue: cp.async tile 0 into buffer 0
#pragma unroll
  for (int p = 0; p < 4; p++) {
    int r = cr + p * 32;
    uint32_t so = (uint32_t)(r * ATW + cc4) * 4u;
    CP_ASYNC16(sbase + AT_Q0 * 4u + so, qp2 + (size_t)r * 64 + cc4);
    CP_ASYNC16(sbase + AT_V0 * 4u + so, vp2 + (size_t)r * 64 + cc4);
  }
  CP_COMMIT();

  const int lg = lane >> 3;
  const int vrow0 = (lane & 7) + ((lg & 1) << 3);
  const int vn0 = (wn >> 1) + ((lg >> 1) << 2);

  float O[2][4][4];
#pragma unroll
  for (int mt = 0; mt < 2; mt++)
#pragma unroll
    for (int nt = 0; nt < 4; nt++)
#pragma unroll
      for (int e = 0; e < 4; e++) O[mt][nt][e] = 0.f;
  float L[4] = {0.f, 0.f, 0.f, 0.f};

  const int row_rel[4] = {qr, qr + 8, qr + 16, qr + 24};

  for (int jt = 0; jt < NSEQ / 128; jt++) {
    const int j0 = jt * 128;
    __syncthreads();  // (A) prev PV done -> next buffer & P free

    if (jt < NSEQ / 128 - 1) {
      const int jn = j0 + 128;
      const uint32_t qoff = ((jt + 1) & 1) ? AT_Q1 : AT_Q0;
      const uint32_t voff = ((jt + 1) & 1) ? AT_V1 : AT_V0;
#pragma unroll
      for (int p = 0; p < 4; p++) {
        int r = cr + p * 32;
        uint32_t so = (uint32_t)(r * ATW + cc4) * 4u;
        CP_ASYNC16(sbase + qoff * 4u + so, qp2 + (size_t)(jn + r) * 64 + cc4);
        CP_ASYNC16(sbase + voff * 4u + so, vp2 + (size_t)(jn + r) * 64 + cc4);
      }
      CP_COMMIT();
      CP_WAIT1();
    } else {
      CP_WAIT0();
    }
    __syncthreads();  // (B) tile jt resident

    const uint32_t* Qs2 = smu + ((jt & 1) ? AT_Q1 : AT_Q0);
    const uint32_t vbase = sbase + ((jt & 1) ? AT_V1 : AT_V0) * 4u;

    // ---- S = K · Q^T
    float S[2][4][4];
#pragma unroll
    for (int mt = 0; mt < 2; mt++)
#pragma unroll
      for (int nt = 0; nt < 4; nt++)
#pragma unroll
        for (int e = 0; e < 4; e++) S[mt][nt][e] = 0.f;

#pragma unroll
    for (int ks = 0; ks < 8; ks++) {
      const int k8 = ks * 8;
      uint32_t A[2][4];
#pragma unroll
      for (int mt = 0; mt < 2; mt++) {
        const uint32_t* ab = Ks2 + (wm + mt * 16 + qr) * ATW + k8 + qc;
        A[mt][0] = ab[0];
        A[mt][1] = ab[8 * ATW];
        A[mt][2] = ab[4];
        A[mt][3] = ab[8 * ATW + 4];
      }
#pragma unroll
      for (int nt = 0; nt < 4; nt++) {
        const uint32_t* bb = Qs2 + (wn + nt * 8 + qr) * ATW + k8 + qc;
        uint32_t b0 = bb[0], b1 = bb[4];
        mma_f16(S[0][nt], A[0], b0, b1);
        mma_f16(S[1][nt], A[1], b0, b1);
      }
    }

    // ---- masked exp
    const unsigned* mb = g_mbits + (size_t)((j0 + wn) >> 5) * NSEQ + i0 + wm;
    unsigned mw[4];
#pragma unroll
    for (int r = 0; r < 4; r++) mw[r] = mb[row_rel[r]];

    float lacc[4] = {0.f, 0.f, 0.f, 0.f};
#pragma unroll
    for (int mt = 0; mt < 2; mt++) {
#pragma unroll
      for (int nt = 0; nt < 4; nt++) {
        const int b0 = nt * 8 + 2 * qc;
        const unsigned w0 = mw[mt * 2], w1 = mw[mt * 2 + 1];
        float* s = S[mt][nt];
        float p0 = ((w0 >> b0) & 1u) ? exp2f(s[0] * C2) : 0.f;
        float p1 = ((w0 >> (b0 + 1)) & 1u) ? exp2f(s[1] * C2) : 0.f;
        float p2 = ((w1 >> b0) & 1u) ? exp2f(s[2] * C2) : 0.f;
        float p3 = ((w1 >> (b0 + 1)) & 1u) ? exp2f(s[3] * C2) : 0.f;
        s[0] = p0; s[1] = p1; s[2] = p2; s[3] = p3;
        lacc[mt * 2] += p0 + p1;
        lacc[mt * 2 + 1] += p2 + p3;
      }
    }
#pragma unroll
    for (int r = 0; r < 4; r++) {
      float v = lacc[r];
      v += __shfl_xor_sync(0xffffffffu, v, 1);
      v += __shfl_xor_sync(0xffffffffu, v, 2);
      L[r] += v;
    }

    // ---- P -> smem as f16x2
#pragma unroll
    for (int mt = 0; mt < 2; mt++) {
#pragma unroll
      for (int nt = 0; nt < 4; nt++) {
        const int row0 = wm + mt * 16 + qr;
        const int cu = (wn >> 1) + nt * 4 + qc;
        const float* s = S[mt][nt];
        Ps2[row0 * ATW + cu] = f2h2(s[0], s[1]);
        Ps2[(row0 + 8) * ATW + cu] = f2h2(s[2], s[3]);
      }
    }
    __syncthreads();  // (C) P complete

    // ---- O += P · V
    uint32_t vaddr0 = vbase + (uint32_t)(vrow0 * ATW + vn0) * 4u;
    uint32_t vaddr1 = vaddr0 + 32u;
#pragma unroll
    for (int ks = 0; ks < 8; ks++) {
      const int k8 = ks * 8;
      uint32_t A[2][4];
#pragma unroll
      for (int mt = 0; mt < 2; mt++) {
        const uint32_t* ab = Ps2 + (wm + mt * 16 + qr) * ATW + k8 + qc;
        A[mt][0] = ab[0];
        A[mt][1] = ab[8 * ATW];
        A[mt][2] = ab[4];
        A[mt][3] = ab[8 * ATW + 4];
      }
      uint32_t b0, b1, b2, b3;
      ldmatrix_x4_trans(b0, b1, b2, b3, vaddr0);
      mma_f16(O[0][0], A[0], b0, b1);
      mma_f16(O[1][0], A[1], b0, b1);
      mma_f16(O[0][1], A[0], b2, b3);
      mma_f16(O[1][1], A[1], b2, b3);
      ldmatrix_x4_trans(b0, b1, b2, b3, vaddr1);
      mma_f16(O[0][2], A[0], b0, b1);
      mma_f16(O[1][2], A[1], b0, b1);
      mma_f16(O[0][3], A[0], b2, b3);
      mma_f16(O[1][3], A[1], b2, b3);
      vaddr0 += 16u * ATW * 4u;
      vaddr1 += 16u * ATW * 4u;
    }
  }

  // combine row sums
  if (qc == 0) {
#pragma unroll
    for (int r = 0; r < 4; r++)
      l_sh[(wid >> 2) * 128 + wm + row_rel[r]] = L[r];
  }
  __syncthreads();
  float linv[4];
#pragma unroll
  for (int r = 0; r < 4; r++) {
    int row = wm + row_rel[r];
    linv[r] = 1.f / (l_sh[row] + l_sh[128 + row] + l_sh[256 + row] + l_sh[384 + row]);
  }

  // epilogue: write ctx as packed f16x2
#pragma unroll
  for (int mt = 0; mt < 2; mt++) {
#pragma unroll
    for (int nt = 0; nt < 4; nt++) {
      const int row0 = wm + mt * 16 + qr;
      const int cu = h * 64 + (wn >> 1) + nt * 4 + qc;
      const float* o = O[mt][nt];
      g_ctx2[(size_t)(i0 + row0) * 1024 + cu] =
          f2h2(o[0] * linv[mt * 2], o[1] * linv[mt * 2]);
      g_ctx2[(size_t)(i0 + row0 + 8) * 1024 + cu] =
          f2h2(o[2] * linv[mt * 2 + 1], o[3] * linv[mt * 2 + 1]);
    }
  }
}

// ======================= kernel 3: out (f16, split-K 16, 2/SM) ===============
// per block: kc covers 128 k. Xs = packed ctx slice (direct copy);
// Bt = last^T packed f16.
__global__ void __launch_bounds__(256) out_tc_kernel(const float* __restrict__ last) {
  extern __shared__ uint32_t smg[];
  uint32_t* Xs = smg;
  uint32_t* Bt = smg + 128 * GW;

  const int m0 = blockIdx.x * 128;
  const int kc = blockIdx.y;
  const int kb = kc * 128;
  const int tid = threadIdx.x;
  const int wid = tid >> 5;
  const int lane = tid & 31;
  const int qr = lane >> 2, qc = lane & 3;
  const int wm = (wid & 3) * 32;
  const int wn = (wid >> 2) * 64;

  // X: direct uint4 copy of packed ctx
  for (int idx = tid; idx < 128 * 16; idx += 256) {
    int r = idx >> 4, c4 = (idx & 15) << 2;
    uint4 t = *reinterpret_cast<const uint4*>(
        g_ctx2 + (size_t)(m0 + r) * 1024 + (kb >> 1) + c4);
    *reinterpret_cast<uint4*>(Xs + r * GW + c4) = t;
  }
  // B^T: pack last[k][e] pairs along k
  for (int idx = tid; idx < 128 * 32; idx += 256) {
    int e = idx & 127, k4 = (idx >> 7) << 2;
    *reinterpret_cast<uint2*>(Bt + e * GW + (k4 >> 1)) = make_uint2(
        f2h2(last[(size_t)(kb + k4 + 0) * DIMD + e], last[(size_t)(kb + k4 + 1) * DIMD + e]),
        f2h2(last[(size_t)(kb + k4 + 2) * DIMD + e], last[(size_t)(kb + k4 + 3) * DIMD + e]));
  }
  __syncthreads();

  float O[2][8][4];
#pragma unroll
  for (int mt = 0; mt < 2; mt++)
#pragma unroll
    for (int nt = 0; nt < 8; nt++)
#pragma unroll
      for (int e = 0; e < 4; e++) O[mt][nt][e] = 0.f;

#pragma unroll
  for (int ks = 0; ks < 8; ks++) {
    const int k8 = ks * 8;
    uint32_t Af[2][4];
#pragma unroll
    for (int mt = 0; mt < 2; mt++) {
      const uint32_t* ab = Xs + (wm + mt * 16 + qr) * GW + k8 + qc;
      Af[mt][0] = ab[0];
      Af[mt][1] = ab[8 * GW];
      Af[mt][2] = ab[4];
      Af[mt][3] = ab[8 * GW + 4];
    }
#pragma unroll
    for (int nt = 0; nt < 8; nt++) {
      const uint32_t* bb = Bt + (wn + nt * 8 + qr) * GW + k8 + qc;
      uint32_t b0 = bb[0], b1 = bb[4];
      mma_f16(O[0][nt], Af[0], b0, b1);
      mma_f16(O[1][nt], Af[1], b0, b1);
    }
  }

  float* Pb = g_part + (size_t)kc * NSEQ * DIMD + (size_t)m0 * DIMD;
#pragma unroll
  for (int mt = 0; mt < 2; mt++) {
#pragma unroll
    for (int nt = 0; nt < 8; nt++) {
      const int row0 = wm + mt * 16 + qr;
      const int col = wn + nt * 8 + 2 * qc;
      const float* o = O[mt][nt];
      *reinterpret_cast<float2*>(Pb + (size_t)row0 * DIMD + col) = make_float2(o[0], o[1]);
      *reinterpret_cast<float2*>(Pb + (size_t)(row0 + 8) * DIMD + col) = make_float2(o[2], o[3]);
    }
  }
}

__global__ void __launch_bounds__(256) reduce_kernel(float* __restrict__ out) {
  int i = blockIdx.x * 256 + threadIdx.x;
  const float4* p = reinterpret_cast<const float4*>(g_part);
  float4 a = p[i];
#pragma unroll
  for (int kc = 1; kc < KSPLIT; kc++) {
    float4 b = p[(size_t)kc * (NSEQ * DIMD / 4) + i];
    a.x += b.x; a.y += b.y; a.z += b.z; a.w += b.w;
  }
  reinterpret_cast<float4*>(out)[i] = a;
}

// =====================================================================
extern "C" void kernel_launch(void* const* d_in, const int* in_sizes, int n_in,
                              void* d_out, int out_size) {
  int mi = -1;
  for (int i = 0; i < n_in; i++)
    if (in_sizes[i] == NSEQ * NSEQ) { mi = i; break; }
  if (mi < 0) mi = 3;

  const void* p[7];
  int np = 0;
  for (int i = 0; i < n_in && np < 7; i++) {
    if (i == mi) continue;
    p[np++] = d_in[i];
  }
  const float* q = (const float*)p[0];
  const float* k = (const float*)p[1];
  const float* v = (const float*)p[2];
  const float* Qw = (const float*)p[3];
  const float* Kw = (const float*)p[4];
  const float* Vw = (const float*)p[5];
  const float* last = (const float*)p[6];
  const int* mask = (const int*)d_in[mi];
  float* out = (float*)d_out;

  const int GEMM_SMEM = 2 * 128 * GW * 4;  // 69,632 B -> 2 blocks/SM

  cudaFuncSetAttribute(proj_tc_kernel, cudaFuncAttributeMaxDynamicSharedMemorySize, GEMM_SMEM);
  cudaFuncSetAttribute(out_tc_kernel, cudaFuncAttributeMaxDynamicSharedMemorySize, GEMM_SMEM);
  cudaFuncSetAttribute(attn_mma_kernel, cudaFuncAttributeMaxDynamicSharedMemorySize,
                       ATTN_SMEM_BYTES);

  maskbits_kernel<<<NSEQ * (NSEQ / 32) / 8, 256>>>(mask);
  proj_tc_kernel<<<dim3(NSEQ / 128, HEADS, 3), 256, GEMM_SMEM>>>(q, k, v, Qw, Kw, Vw);
  attn_mma_kernel<<<dim3(NSEQ / 128, HEADS), 512, ATTN_SMEM_BYTES>>>();
  out_tc_kernel<<<dim3(NSEQ / 128, KSPLIT), 256, GEMM_SMEM>>>(last);
  reduce_kernel<<<NSEQ * DIMD / 4 / 256, 256>>>(out);
}